// round 5
// baseline (speedup 1.0000x reference)
#include <cuda_runtime.h>
#include <math.h>
#include <stdint.h>

// Problem constants
#define NTOK 16384
#define DIM  2048
#define NEXP 64
#define NK   (NTOK * 2)          // 32768 (token, slot) pairs

// GEMM tiling
#define BM 128                   // tokens per CTA
#define KC 16                    // fp32 per K-chunk
#define NCHUNK (DIM / KC)        // 128
#define GTHREADS 256
#define NBLK (NTOK / BM)         // 128 CTAs

// Output layout: concatenation of reference return values (all as fp32)
#define OFF_TOK   0
#define OFF_REV   NK
#define OFF_CW    (2 * NK)
#define OFF_SPL   (3 * NK)
#define OFF_PROBS (3 * NK + NEXP)

// smem stage layout (float2 units):
//  AH: [2 ks][4 q][128 row(^4q swizzle)]   = 1024 float2  (8192 B)
//  AL: same                                 = 1024 float2
//  WH: [2 ks][4 k][68 n]                    = 544  float2  (4352 B)
//  WL: same                                 = 544  float2
#define AH_F2   1024
#define WH_F2   544
#define STAGE_BYTES ((2 * AH_F2 + 2 * WH_F2) * 8)   // 25088
#define SMEM_DYN (2 * STAGE_BYTES + 128)

// Scratch (no allocations allowed -> __device__ globals)
__device__ int g_flat_idx[NK];
__device__ int g_blockHist[NBLK * NEXP];
__device__ int g_blockBase[NBLK * NEXP];

// ---------------------------------------------------------------------------
__device__ __forceinline__ void split_tf32(float a, uint32_t& h, uint32_t& l) {
    asm("cvt.rna.tf32.f32 %0, %1;" : "=r"(h) : "f"(a));
    float lo = a - __uint_as_float(h);
    asm("cvt.rna.tf32.f32 %0, %1;" : "=r"(l) : "f"(lo));
}

#define MMA_TF32(c, a0, a1, a2, a3, b0, b1)                                   \
    asm volatile(                                                             \
        "mma.sync.aligned.m16n8k8.row.col.f32.tf32.tf32.f32 "                 \
        "{%0,%1,%2,%3}, {%4,%5,%6,%7}, {%8,%9}, {%0,%1,%2,%3};"               \
        : "+f"((c)[0]), "+f"((c)[1]), "+f"((c)[2]), "+f"((c)[3])              \
        : "r"(a0), "r"(a1), "r"(a2), "r"(a3), "r"(b0), "r"(b1))

// ---------------------------------------------------------------------------
// Kernel 1: tf32-split mma.sync GEMM + softmax + top-2 + combine + probs + hist
// 8 warps: warp = mG(0..3) x nG(0..1); warp tile M32 x N32.
// ---------------------------------------------------------------------------
__global__ __launch_bounds__(GTHREADS) void gate_gemm_kernel(
    const float* __restrict__ A,   // [NTOK, DIM]
    const float* __restrict__ W,   // [NEXP, DIM]
    float* __restrict__ out)
{
    extern __shared__ char dynsm[];
    char* sbase = (char*)(((uintptr_t)dynsm + 127) & ~(uintptr_t)127);

    __shared__ int hist[NEXP];

    const int tid  = threadIdx.x;
    const int wid  = tid >> 5;
    const int lane = tid & 31;
    const int g    = lane >> 2;       // fragment group 0..7
    const int q    = lane & 3;        // fragment quad  0..3
    const int mG   = wid >> 1;        // rows 32*mG
    const int nG   = wid & 1;         // cols 32*nG
    const int blk  = blockIdx.x;
    const int tok0 = blk * BM;

    if (tid < NEXP) hist[tid] = 0;

    // loader geometry
    const int arow = tid & 127;       // A row
    const int aks  = tid >> 7;        // A k8-block
    const int wn   = tid & 63;        // W expert
    const int wks  = (tid >> 6) & 1;  // W k8-block (tid<128 active)

    const float* Asrc = A + (size_t)(tok0 + arow) * DIM + 8 * aks;
    const float* Wsrc = W + (size_t)wn * DIM + 8 * wks;

    float4 pa0, pa1, pw0, pw1;
    auto ldRegs = [&](int t) {
        const float* s = Asrc + t * KC;
        pa0 = *reinterpret_cast<const float4*>(s);
        pa1 = *reinterpret_cast<const float4*>(s + 4);
        if (tid < 128) {
            const float* w = Wsrc + t * KC;
            pw0 = *reinterpret_cast<const float4*>(w);
            pw1 = *reinterpret_cast<const float4*>(w + 4);
        }
    };
    auto stStage = [&](int s) {
        float2* AH = reinterpret_cast<float2*>(sbase + s * STAGE_BYTES);
        float2* AL = AH + AH_F2;
        float2* WH = AL + AH_F2;
        float2* WL = WH + WH_F2;
        const float au[4] = {pa0.x, pa0.y, pa0.z, pa0.w};
        const float av[4] = {pa1.x, pa1.y, pa1.z, pa1.w};
#pragma unroll
        for (int qq = 0; qq < 4; ++qq) {
            uint32_t hx, lx, hy, ly;
            split_tf32(au[qq], hx, lx);
            split_tf32(av[qq], hy, ly);
            int idx = aks * 512 + qq * 128 + (arow ^ (qq << 2));
            AH[idx] = make_float2(__uint_as_float(hx), __uint_as_float(hy));
            AL[idx] = make_float2(__uint_as_float(lx), __uint_as_float(ly));
        }
        if (tid < 128) {
            const float wu[4] = {pw0.x, pw0.y, pw0.z, pw0.w};
            const float wv[4] = {pw1.x, pw1.y, pw1.z, pw1.w};
#pragma unroll
            for (int qq = 0; qq < 4; ++qq) {
                uint32_t hx, lx, hy, ly;
                split_tf32(wu[qq], hx, lx);
                split_tf32(wv[qq], hy, ly);
                int idx = wks * 272 + qq * 68 + wn;
                WH[idx] = make_float2(__uint_as_float(hx), __uint_as_float(hy));
                WL[idx] = make_float2(__uint_as_float(lx), __uint_as_float(ly));
            }
        }
    };

    float acc[2][4][4];
#pragma unroll
    for (int mt = 0; mt < 2; ++mt)
#pragma unroll
        for (int nt = 0; nt < 4; ++nt)
#pragma unroll
            for (int c = 0; c < 4; ++c) acc[mt][nt][c] = 0.f;

    // prologue
    ldRegs(0);
    stStage(0);
    ldRegs(1);

    for (int t = 0; t < NCHUNK; ++t) {
        __syncthreads();
        if (t + 1 < NCHUNK) {
            stStage((t + 1) & 1);
            if (t + 2 < NCHUNK) ldRegs(t + 2);
        }
        // compute chunk t from stage t&1
        const float2* AH = reinterpret_cast<const float2*>(sbase + (t & 1) * STAGE_BYTES);
        const float2* AL = AH + AH_F2;
        const float2* WH = AL + AH_F2;
        const float2* WL = WH + WH_F2;

#pragma unroll
        for (int ks = 0; ks < 2; ++ks) {
            uint32_t aH[2][4], aL[2][4];
#pragma unroll
            for (int mt = 0; mt < 2; ++mt) {
                int rb = 32 * mG + 16 * mt;
                int i0 = ks * 512 + q * 128 + ((rb + g) ^ (q << 2));
                int i1 = ks * 512 + q * 128 + ((rb + 8 + g) ^ (q << 2));
                float2 h0 = AH[i0], h1 = AH[i1];
                float2 l0 = AL[i0], l1 = AL[i1];
                aH[mt][0] = __float_as_uint(h0.x); aH[mt][1] = __float_as_uint(h1.x);
                aH[mt][2] = __float_as_uint(h0.y); aH[mt][3] = __float_as_uint(h1.y);
                aL[mt][0] = __float_as_uint(l0.x); aL[mt][1] = __float_as_uint(l1.x);
                aL[mt][2] = __float_as_uint(l0.y); aL[mt][3] = __float_as_uint(l1.y);
            }
#pragma unroll
            for (int nt = 0; nt < 4; ++nt) {
                int n = 32 * nG + 8 * nt + g;
                int bi = ks * 272 + q * 68 + n;
                float2 bh = WH[bi], bl = WL[bi];
                uint32_t bH0 = __float_as_uint(bh.x), bH1 = __float_as_uint(bh.y);
                uint32_t bL0 = __float_as_uint(bl.x), bL1 = __float_as_uint(bl.y);
#pragma unroll
                for (int mt = 0; mt < 2; ++mt) {
                    MMA_TF32(acc[mt][nt], aH[mt][0], aH[mt][1], aH[mt][2], aH[mt][3], bH0, bH1);
                    MMA_TF32(acc[mt][nt], aH[mt][0], aH[mt][1], aH[mt][2], aH[mt][3], bL0, bL1);
                    MMA_TF32(acc[mt][nt], aL[mt][0], aL[mt][1], aL[mt][2], aL[mt][3], bH0, bH1);
                }
            }
        }
    }

    // ---- epilogue: stage logits in smem (reuse stage area) -----------------
    __syncthreads();
    float* Cs = reinterpret_cast<float*>(sbase);      // [128][66]
#pragma unroll
    for (int mt = 0; mt < 2; ++mt)
#pragma unroll
        for (int nt = 0; nt < 4; ++nt) {
            int row = 32 * mG + 16 * mt + g;
            int col = 32 * nG + 8 * nt + 2 * q;
            *reinterpret_cast<float2*>(&Cs[row * 66 + col]) =
                make_float2(acc[mt][nt][0], acc[mt][nt][1]);
            *reinterpret_cast<float2*>(&Cs[(row + 8) * 66 + col]) =
                make_float2(acc[mt][nt][2], acc[mt][nt][3]);
        }
    __syncthreads();

    if (tid < BM) {                     // one thread per token
        const int t = tid;
        float f[64];
        float mx = -1e30f;
#pragma unroll
        for (int e = 0; e < NEXP; e++) { f[e] = Cs[t * 66 + e]; mx = fmaxf(mx, f[e]); }
        float ssum = 0.f;
#pragma unroll
        for (int e = 0; e < NEXP; e++) { f[e] = expf(f[e] - mx); ssum += f[e]; }
        float inv = 1.0f / ssum;
        float v1 = -1.f, v2 = -1.f;
        int i1 = 0, i2 = 0;
#pragma unroll
        for (int e = 0; e < NEXP; e++) {
            float p = f[e] * inv;
            f[e] = p;
            if (p > v1)      { v2 = v1; i2 = i1; v1 = p; i1 = e; }
            else if (p > v2) { v2 = p; i2 = e; }
        }
        // combine = softmax over the top-2 prob VALUES (reference quirk)
        float eb = expf(v2 - v1);
        float invd = 1.0f / (1.0f + eb);
        const int token = tok0 + t;
        const int flat = token * 2;
        out[OFF_CW + flat]     = invd;
        out[OFF_CW + flat + 1] = eb * invd;
        g_flat_idx[flat]     = i1;
        g_flat_idx[flat + 1] = i2;
        atomicAdd(&hist[i1], 1);
        atomicAdd(&hist[i2], 1);
        // probs written back per token (contiguous 256B)
        float4* pp = reinterpret_cast<float4*>(out + OFF_PROBS + (size_t)token * NEXP);
#pragma unroll
        for (int k = 0; k < 16; k++)
            pp[k] = make_float4(f[4 * k], f[4 * k + 1], f[4 * k + 2], f[4 * k + 3]);
    }
    __syncthreads();

    if (tid < NEXP) g_blockHist[blk * NEXP + tid] = hist[tid];
}

// ---------------------------------------------------------------------------
// Kernel 2 (1 CTA, 1024 threads): per-expert scan across blocks + offsets
// ---------------------------------------------------------------------------
#define CHUNK (NBLK / 16)        // 8 blocks per chunk
__global__ __launch_bounds__(1024) void gate_scan_kernel(float* __restrict__ out)
{
    __shared__ int part[16][NEXP];
    __shared__ int totals[NEXP];
    __shared__ int offs[NEXP];
    const int tid = threadIdx.x;
    const int e = tid & 63;
    const int c = tid >> 6;          // chunk 0..15

    int s = 0;
#pragma unroll
    for (int b = c * CHUNK; b < (c + 1) * CHUNK; b++) s += g_blockHist[b * NEXP + e];
    part[c][e] = s;
    __syncthreads();

    if (tid < NEXP) {
        int run = 0;
#pragma unroll
        for (int cc = 0; cc < 16; cc++) run += part[cc][e];
        totals[e] = run;
        out[OFF_SPL + e] = (float)run;
    }
    __syncthreads();

    if (tid == 0) {
        int a = 0;
        for (int i = 0; i < NEXP; i++) { offs[i] = a; a += totals[i]; }
    }
    __syncthreads();

    int base = offs[e];
    for (int cc = 0; cc < c; cc++) base += part[cc][e];
#pragma unroll
    for (int b = c * CHUNK; b < (c + 1) * CHUNK; b++) {
        g_blockBase[b * NEXP + e] = base;
        base += g_blockHist[b * NEXP + e];
    }
}

// ---------------------------------------------------------------------------
// Kernel 3 (NBLK x 256): stable intra-block rank + scatter.
// Block covers 256 flat slots = one histogram block (BM=128 tokens).
// ---------------------------------------------------------------------------
__global__ __launch_bounds__(256) void gate_scatter_kernel(float* __restrict__ out)
{
    __shared__ int warpHist[8][NEXP];
    __shared__ int base_s[NEXP];
    const int tid  = threadIdx.x;
    const int blk  = blockIdx.x;
    const int w    = tid >> 5;
    const int lane = tid & 31;

    if (tid < NEXP) base_s[tid] = g_blockBase[blk * NEXP + tid];
    for (int i = tid; i < 8 * NEXP; i += 256) (&warpHist[0][0])[i] = 0;
    __syncthreads();

    const int flat = blk * 256 + tid;
    const int e    = g_flat_idx[flat];

    unsigned m     = __match_any_sync(0xffffffffu, e);
    unsigned below = m & ((1u << lane) - 1u);
    int rank = __popc(below);
    if (below == 0) warpHist[w][e] = __popc(m);     // lowest lane of group
    __syncthreads();

    int prev = 0;
#pragma unroll
    for (int ww = 0; ww < 7; ++ww)
        if (ww < w) prev += warpHist[ww][e];

    const int pos = base_s[e] + prev + rank;
    out[OFF_TOK + pos]  = (float)(flat >> 1);       // token index
    out[OFF_REV + flat] = (float)pos;               // sorted position of flat idx
}

// ---------------------------------------------------------------------------
extern "C" void kernel_launch(void* const* d_in, const int* in_sizes, int n_in,
                              void* d_out, int out_size)
{
    const float* A = (const float*)d_in[0];   // inputs    [16384, 2048] fp32
    const float* W = (const float*)d_in[1];   // wg_weight [64, 2048]    fp32
    float* out = (float*)d_out;

    cudaFuncSetAttribute(gate_gemm_kernel,
                         cudaFuncAttributeMaxDynamicSharedMemorySize, SMEM_DYN);

    gate_gemm_kernel<<<NBLK, GTHREADS, SMEM_DYN>>>(A, W, out);
    gate_scan_kernel<<<1, 1024>>>(out);
    gate_scatter_kernel<<<NBLK, 256>>>(out);
}

// round 6
// speedup vs baseline: 2.2883x; 2.2883x over previous
#include <cuda_runtime.h>
#include <cuda_bf16.h>
#include <math.h>
#include <stdint.h>

// Problem constants
#define NTOK 16384
#define DIM  2048
#define NEXP 64
#define NK   (NTOK * 2)          // 32768 (token, slot) pairs

// GEMM tiling
#define BM 64                    // tokens per CTA
#define KC 32                    // fp32 per K-chunk (2 k16 MMA steps)
#define NCHUNK (DIM / KC)        // 64
#define GTHREADS 128
#define NBLK (NTOK / BM)         // 256 CTAs

// Output layout: concatenation of reference return values (all as fp32)
#define OFF_TOK   0
#define OFF_REV   NK
#define OFF_CW    (2 * NK)
#define OFF_SPL   (3 * NK)
#define OFF_PROBS (3 * NK + NEXP)

// smem stage layout (bytes): blocked 8x8-bf16 tiles (128B each), 32 tiles per
// matrix half.  A/W: tile(kt,rt) at (kt*8+rt)*128; inner line = (row&7)^(kt*2).
#define AH_OFF 0
#define AL_OFF 4096
#define WH_OFF 8192
#define WL_OFF 12288
#define STAGE_BYTES 16384
#define SMEM_DYN (2 * STAGE_BYTES + 1024)

// Scratch (no allocations allowed -> __device__ globals)
__device__ int g_flat_idx[NK];
__device__ int g_blockHist[NBLK * NEXP];
__device__ int g_blockBase[NBLK * NEXP];

// ---------------------------------------------------------------------------
__device__ __forceinline__ uint32_t smem_u32(const void* p) {
    uint32_t a;
    asm("{ .reg .u64 t; cvta.to.shared.u64 t, %1; cvt.u32.u64 %0, t; }"
        : "=r"(a) : "l"(p));
    return a;
}

#define LDMX4(r0, r1, r2, r3, addr)                                           \
    asm volatile("ldmatrix.sync.aligned.m8n8.x4.shared.b16 {%0,%1,%2,%3}, [%4];" \
        : "=r"(r0), "=r"(r1), "=r"(r2), "=r"(r3) : "r"(addr))

#define MMA_BF16(c, a0, a1, a2, a3, b0, b1)                                   \
    asm volatile(                                                             \
        "mma.sync.aligned.m16n8k16.row.col.f32.bf16.bf16.f32 "                \
        "{%0,%1,%2,%3}, {%4,%5,%6,%7}, {%8,%9}, {%0,%1,%2,%3};"               \
        : "+f"((c)[0]), "+f"((c)[1]), "+f"((c)[2]), "+f"((c)[3])              \
        : "r"(a0), "r"(a1), "r"(a2), "r"(a3), "r"(b0), "r"(b1))

__device__ __forceinline__ uint32_t pack_bf16(__nv_bfloat16 a, __nv_bfloat16 b) {
    __nv_bfloat162 v; v.x = a; v.y = b;
    return *reinterpret_cast<uint32_t*>(&v);
}

// split x,y into hi/lo bf16 pairs packed as bf16x2
__device__ __forceinline__ void split2(float x, float y, uint32_t& hi, uint32_t& lo) {
    __nv_bfloat16 hx = __float2bfloat16(x), hy = __float2bfloat16(y);
    float rx = x - __bfloat162float(hx);
    float ry = y - __bfloat162float(hy);
    hi = pack_bf16(hx, hy);
    lo = pack_bf16(__float2bfloat16(rx), __float2bfloat16(ry));
}

// ---------------------------------------------------------------------------
// Kernel 1: bf16-split mma.sync GEMM + softmax + top-2 + combine + probs + hist
// 4 warps: warp = (mG = wid>>1) x (nG = wid&1); warp tile M32 x N32.
// ---------------------------------------------------------------------------
__global__ __launch_bounds__(GTHREADS, 2) void gate_gemm_kernel(
    const float* __restrict__ A,   // [NTOK, DIM]
    const float* __restrict__ W,   // [NEXP, DIM]
    float* __restrict__ out)
{
    extern __shared__ char dynsm[];
    char* sbase = (char*)(((uintptr_t)dynsm + 1023) & ~(uintptr_t)1023);
    const uint32_t sb = smem_u32(sbase);

    __shared__ int hist[NEXP];

    const int tid  = threadIdx.x;
    const int wid  = tid >> 5;
    const int lane = tid & 31;
    const int g    = lane >> 2;
    const int q    = lane & 3;
    const int lg   = lane >> 3;       // ldmatrix lane group 0..3
    const int lr   = lane & 7;
    const int mG   = wid >> 1;        // rows 32*mG
    const int nG   = wid & 1;         // cols 32*nG
    const int blk  = blockIdx.x;
    const int tok0 = blk * BM;

    if (tid < NEXP) hist[tid] = 0;

    // ---- producer geometry: thread -> (row = t>>3 + 16p, c4 = t&7) ---------
    const int prow = tid >> 3;        // 0..15
    const int c4   = tid & 7;
    const int kt_p = c4 >> 1;
    const int hf_p = c4 & 1;

    const float4* Ap[4];
    const float4* Wp[4];
    uint32_t stOff[4];
#pragma unroll
    for (int p = 0; p < 4; ++p) {
        int r = prow + 16 * p;
        Ap[p] = reinterpret_cast<const float4*>(A + (size_t)(tok0 + r) * DIM + 4 * c4);
        Wp[p] = reinterpret_cast<const float4*>(W + (size_t)r * DIM + 4 * c4);
        stOff[p] = (uint32_t)((kt_p * 8 + (r >> 3)) * 128 +
                              (((r & 7) ^ (kt_p << 1)) << 4) + hf_p * 8);
    }

    float4 pa[4], pw[4];
    auto ldRegs = [&](int t) {
        const int o = t * 8;          // 32 floats = 8 float4
#pragma unroll
        for (int p = 0; p < 4; ++p) { pa[p] = Ap[p][o]; pw[p] = Wp[p][o]; }
    };
    auto stStage = [&](int s) {
        char* stg = sbase + s * STAGE_BYTES;
#pragma unroll
        for (int p = 0; p < 4; ++p) {
            uint2 h, l;
            split2(pa[p].x, pa[p].y, h.x, l.x);
            split2(pa[p].z, pa[p].w, h.y, l.y);
            *reinterpret_cast<uint2*>(stg + AH_OFF + stOff[p]) = h;
            *reinterpret_cast<uint2*>(stg + AL_OFF + stOff[p]) = l;
            split2(pw[p].x, pw[p].y, h.x, l.x);
            split2(pw[p].z, pw[p].w, h.y, l.y);
            *reinterpret_cast<uint2*>(stg + WH_OFF + stOff[p]) = h;
            *reinterpret_cast<uint2*>(stg + WL_OFF + stOff[p]) = l;
        }
    };

    float acc[2][4][4];
#pragma unroll
    for (int mt = 0; mt < 2; ++mt)
#pragma unroll
        for (int nt = 0; nt < 4; ++nt)
#pragma unroll
            for (int c = 0; c < 4; ++c) acc[mt][nt][c] = 0.f;

    // consumer lane-constant pieces
    const uint32_t aRt = (uint32_t)((4 * mG + (lg & 1)) * 128);
    const uint32_t wRt = (uint32_t)((4 * nG + (lg >> 1)) * 128);

    // prologue
    ldRegs(0);
    stStage(0);
    ldRegs(1);

    for (int t = 0; t < NCHUNK; ++t) {
        __syncthreads();
        if (t + 1 < NCHUNK) {
            stStage((t + 1) & 1);
            if (t + 2 < NCHUNK) ldRegs(t + 2);
        }
        const uint32_t stg = sb + (uint32_t)((t & 1) * STAGE_BYTES);

#pragma unroll
        for (int ks = 0; ks < 2; ++ks) {
            const int ktA = 2 * ks + (lg >> 1);
            const int ktW = 2 * ks + (lg & 1);
            const uint32_t aAddr = stg + (uint32_t)(ktA * 1024) +
                                   (uint32_t)(((lr ^ (ktA << 1)) << 4)) + aRt;
            const uint32_t wAddr = stg + WH_OFF + (uint32_t)(ktW * 1024) +
                                   (uint32_t)(((lr ^ (ktW << 1)) << 4)) + wRt;

            uint32_t ah[8], al[8], wh[8], wl[8];
            LDMX4(ah[0], ah[1], ah[2], ah[3], aAddr);
            LDMX4(ah[4], ah[5], ah[6], ah[7], aAddr + 256);
            LDMX4(al[0], al[1], al[2], al[3], aAddr + AL_OFF);
            LDMX4(al[4], al[5], al[6], al[7], aAddr + AL_OFF + 256);
            LDMX4(wh[0], wh[1], wh[2], wh[3], wAddr);
            LDMX4(wh[4], wh[5], wh[6], wh[7], wAddr + 256);
            LDMX4(wl[0], wl[1], wl[2], wl[3], wAddr + 4096);
            LDMX4(wl[4], wl[5], wl[6], wl[7], wAddr + 4096 + 256);

#pragma unroll
            for (int nt = 0; nt < 4; ++nt) {
                const uint32_t bh0 = wh[2 * nt], bh1 = wh[2 * nt + 1];
                const uint32_t bl0 = wl[2 * nt], bl1 = wl[2 * nt + 1];
#pragma unroll
                for (int mt = 0; mt < 2; ++mt) {
                    uint32_t* aH = &ah[4 * mt];
                    uint32_t* aL = &al[4 * mt];
                    MMA_BF16(acc[mt][nt], aH[0], aH[1], aH[2], aH[3], bh0, bh1);
                    MMA_BF16(acc[mt][nt], aH[0], aH[1], aH[2], aH[3], bl0, bl1);
                    MMA_BF16(acc[mt][nt], aL[0], aL[1], aL[2], aL[3], bh0, bh1);
                }
            }
        }
    }

    // ---- epilogue: logits -> Cs (reuse stage smem) -------------------------
    __syncthreads();
    float* Cs = reinterpret_cast<float*>(sbase);      // [64][66]
#pragma unroll
    for (int mt = 0; mt < 2; ++mt)
#pragma unroll
        for (int nt = 0; nt < 4; ++nt) {
            int row = 32 * mG + 16 * mt + g;
            int col = 32 * nG + 8 * nt + 2 * q;
            *reinterpret_cast<float2*>(&Cs[row * 66 + col]) =
                make_float2(acc[mt][nt][0], acc[mt][nt][1]);
            *reinterpret_cast<float2*>(&Cs[(row + 8) * 66 + col]) =
                make_float2(acc[mt][nt][2], acc[mt][nt][3]);
        }
    __syncthreads();

    if (tid < BM) {                     // one thread per token
        const int t = tid;
        float f[64];
        float mx = -1e30f;
#pragma unroll
        for (int e = 0; e < NEXP; e++) { f[e] = Cs[t * 66 + e]; mx = fmaxf(mx, f[e]); }
        float ssum = 0.f;
#pragma unroll
        for (int e = 0; e < NEXP; e++) { f[e] = expf(f[e] - mx); ssum += f[e]; }
        float inv = 1.0f / ssum;
        float v1 = -1.f, v2 = -1.f;
        int i1 = 0, i2 = 0;
#pragma unroll
        for (int e = 0; e < NEXP; e++) {
            float p = f[e] * inv;
            Cs[t * 66 + e] = p;         // probs back to smem for coalesced copy
            if (p > v1)      { v2 = v1; i2 = i1; v1 = p; i1 = e; }
            else if (p > v2) { v2 = p; i2 = e; }
        }
        // combine = softmax over the top-2 prob VALUES (reference quirk)
        float eb = expf(v2 - v1);
        float invd = 1.0f / (1.0f + eb);
        const int token = tok0 + t;
        const int flat = token * 2;
        out[OFF_CW + flat]     = invd;
        out[OFF_CW + flat + 1] = eb * invd;
        g_flat_idx[flat]     = i1;
        g_flat_idx[flat + 1] = i2;
        atomicAdd(&hist[i1], 1);
        atomicAdd(&hist[i2], 1);
    }
    __syncthreads();

    if (tid < NEXP) g_blockHist[blk * NEXP + tid] = hist[tid];

    // coalesced probs writeback
    float* pout = out + OFF_PROBS + (size_t)tok0 * NEXP;
    for (int idx = tid; idx < BM * NEXP; idx += GTHREADS) {
        int tt = idx >> 6, e = idx & 63;
        pout[idx] = Cs[tt * 66 + e];
    }
}

// ---------------------------------------------------------------------------
// Kernel 2 (1 CTA, 1024 threads): per-expert scan across blocks + offsets
// ---------------------------------------------------------------------------
#define CHUNK (NBLK / 16)        // 16 blocks per chunk
__global__ __launch_bounds__(1024) void gate_scan_kernel(float* __restrict__ out)
{
    __shared__ int part[16][NEXP];
    __shared__ int totals[NEXP];
    __shared__ int offs[NEXP];
    const int tid = threadIdx.x;
    const int e = tid & 63;
    const int c = tid >> 6;          // chunk 0..15

    int s = 0;
#pragma unroll
    for (int b = c * CHUNK; b < (c + 1) * CHUNK; b++) s += g_blockHist[b * NEXP + e];
    part[c][e] = s;
    __syncthreads();

    if (tid < NEXP) {
        int run = 0;
#pragma unroll
        for (int cc = 0; cc < 16; cc++) run += part[cc][e];
        totals[e] = run;
        out[OFF_SPL + e] = (float)run;
    }
    __syncthreads();

    if (tid == 0) {
        int a = 0;
        for (int i = 0; i < NEXP; i++) { offs[i] = a; a += totals[i]; }
    }
    __syncthreads();

    int base = offs[e];
    for (int cc = 0; cc < c; cc++) base += part[cc][e];
#pragma unroll
    for (int b = c * CHUNK; b < (c + 1) * CHUNK; b++) {
        g_blockBase[b * NEXP + e] = base;
        base += g_blockHist[b * NEXP + e];
    }
}

// ---------------------------------------------------------------------------
// Kernel 3 (NBLK x 128): stable intra-block rank + scatter.
// Block covers 128 flat slots = one histogram block (BM=64 tokens x 2).
// ---------------------------------------------------------------------------
__global__ __launch_bounds__(128) void gate_scatter_kernel(float* __restrict__ out)
{
    __shared__ int warpHist[4][NEXP];
    __shared__ int base_s[NEXP];
    const int tid  = threadIdx.x;
    const int blk  = blockIdx.x;
    const int w    = tid >> 5;
    const int lane = tid & 31;

    if (tid < NEXP) base_s[tid] = g_blockBase[blk * NEXP + tid];
    for (int i = tid; i < 4 * NEXP; i += 128) (&warpHist[0][0])[i] = 0;
    __syncthreads();

    const int flat = blk * 128 + tid;
    const int e    = g_flat_idx[flat];

    unsigned m     = __match_any_sync(0xffffffffu, e);
    unsigned below = m & ((1u << lane) - 1u);
    int rank = __popc(below);
    if (below == 0) warpHist[w][e] = __popc(m);     // lowest lane of group
    __syncthreads();

    int prev = 0;
#pragma unroll
    for (int ww = 0; ww < 3; ++ww)
        if (ww < w) prev += warpHist[ww][e];

    const int pos = base_s[e] + prev + rank;
    out[OFF_TOK + pos]  = (float)(flat >> 1);       // token index
    out[OFF_REV + flat] = (float)pos;               // sorted position of flat idx
}

// ---------------------------------------------------------------------------
extern "C" void kernel_launch(void* const* d_in, const int* in_sizes, int n_in,
                              void* d_out, int out_size)
{
    const float* A = (const float*)d_in[0];   // inputs    [16384, 2048] fp32
    const float* W = (const float*)d_in[1];   // wg_weight [64, 2048]    fp32
    float* out = (float*)d_out;

    cudaFuncSetAttribute(gate_gemm_kernel,
                         cudaFuncAttributeMaxDynamicSharedMemorySize, SMEM_DYN);

    gate_gemm_kernel<<<NBLK, GTHREADS, SMEM_DYN>>>(A, W, out);
    gate_scan_kernel<<<1, 1024>>>(out);
    gate_scatter_kernel<<<NK / 128, 128>>>(out);
}